// round 3
// baseline (speedup 1.0000x reference)
#include <cuda_runtime.h>
#include <cuda_bf16.h>

#define N_NODES 100000
#define N_EDGES 1600000
#define N_GRAPHS 512
#define DIM 64
#define CAP 64
#define OVF_CAP 8192

// -------- scratch (device globals: no allocation allowed) --------
__device__ int   g_cnt[N_NODES];            // in-degree (real edges only)
__device__ int   g_col[N_NODES * CAP];      // ELL: sources per dst
__device__ float g_dinv[N_NODES];           // rsqrt(deg incl self-loop)
__device__ float g_tmp[N_NODES * DIM];      // GEMM output
__device__ float g_h[N_NODES * DIM];        // aggregation output
__device__ float g_pool[N_GRAPHS * DIM];
__device__ int   g_gcnt[N_GRAPHS];
__device__ int   g_novf;
__device__ int2  g_ovf[OVF_CAP];

// -------- init --------
__global__ void k_init() {
    int i = blockIdx.x * blockDim.x + threadIdx.x;
    if (i < N_NODES) g_cnt[i] = 0;
    if (i < N_GRAPHS * DIM) g_pool[i] = 0.f;
    if (i < N_GRAPHS) g_gcnt[i] = 0;
    if (i == 0) g_novf = 0;
}

// -------- build ELL adjacency (histogram + scatter in one pass) --------
// edge_index is int32 (JAX x64 disabled downcasts int64 -> int32).
__global__ void k_build(const int* __restrict__ ei) {
    int i = blockIdx.x * blockDim.x + threadIdx.x;
    if (i >= N_EDGES) return;
    int src = ei[i];
    int dst = ei[N_EDGES + i];
    if ((unsigned)src >= N_NODES || (unsigned)dst >= N_NODES) return;
    int pos = atomicAdd(&g_cnt[dst], 1);
    if (pos < CAP) {
        g_col[dst * CAP + pos] = src;
    } else {
        int o = atomicAdd(&g_novf, 1);
        if (o < OVF_CAP) g_ovf[o] = make_int2(src, dst);
    }
}

__global__ void k_dinv() {
    int i = blockIdx.x * blockDim.x + threadIdx.x;
    if (i < N_NODES) g_dinv[i] = rsqrtf((float)(g_cnt[i] + 1));
}

// -------- GEMM: g_tmp[N,64] = f(X)[N,64] @ W[64,64] --------
// FROM_H: read g_h (with relu) instead of the external X pointer.
template <bool FROM_H>
__global__ void k_gemm(const float* __restrict__ X, const float* __restrict__ W) {
    __shared__ float Ws[64 * 64];
    __shared__ float Xs[16][64];
    int t = threadIdx.x;
    #pragma unroll
    for (int i = t; i < 64 * 64; i += 256) Ws[i] = W[i];
    int row0 = blockIdx.x * 16;
    #pragma unroll
    for (int i = t; i < 16 * 64; i += 256) {
        int idx = (row0 + (i >> 6)) * 64 + (i & 63);
        float v = FROM_H ? fmaxf(g_h[idx], 0.f) : X[idx];
        Xs[i >> 6][i & 63] = v;
    }
    __syncthreads();
    int r = t >> 4;           // 0..15 (row within block)
    int c = (t & 15) * 4;     // 0,4,...,60 (col group)
    float4 acc = make_float4(0.f, 0.f, 0.f, 0.f);
    #pragma unroll
    for (int k = 0; k < 64; k++) {
        float xv = Xs[r][k];
        const float4 w4 = *(const float4*)&Ws[k * 64 + c];
        acc.x += xv * w4.x;
        acc.y += xv * w4.y;
        acc.z += xv * w4.z;
        acc.w += xv * w4.w;
    }
    *(float4*)&g_tmp[(row0 + r) * 64 + c] = acc;
}

// -------- aggregation: g_h = Agg(g_tmp) + bias; warp per dst node --------
__global__ void k_agg(const float* __restrict__ bias) {
    int warp = (blockIdx.x * blockDim.x + threadIdx.x) >> 5;
    int lane = threadIdx.x & 31;
    if (warp >= N_NODES) return;
    int v = warp;
    float dv = g_dinv[v];
    float2 hv = *(const float2*)&g_tmp[v * 64 + lane * 2];
    float2 acc;
    acc.x = dv * dv * hv.x;   // self-loop term
    acc.y = dv * dv * hv.y;
    int deg = g_cnt[v];
    if (deg > CAP) deg = CAP;
    const int* cols = &g_col[v * CAP];
    for (int base = 0; base < deg; base += 32) {
        int s = 0; float w = 0.f;
        if (base + lane < deg) {
            s = cols[base + lane];
            w = g_dinv[s] * dv;
        }
        int m = min(32, deg - base);
        for (int j = 0; j < m; j++) {
            int   sj = __shfl_sync(0xffffffffu, s, j);
            float wj = __shfl_sync(0xffffffffu, w, j);
            float2 hs = *(const float2*)&g_tmp[sj * 64 + lane * 2];
            acc.x += wj * hs.x;
            acc.y += wj * hs.y;
        }
    }
    float2 b = *(const float2*)&bias[lane * 2];
    acc.x += b.x;
    acc.y += b.y;
    *(float2*)&g_h[v * 64 + lane * 2] = acc;
}

// -------- overflow edges (normally zero) — atomic fallback into g_h --------
__global__ void k_ovf() {
    int n = g_novf;
    if (n > OVF_CAP) n = OVF_CAP;
    for (int idx = blockIdx.x * blockDim.x + threadIdx.x; idx < n * 32;
         idx += gridDim.x * blockDim.x) {
        int e = idx >> 5, lane = idx & 31;
        int2 ed = g_ovf[e];
        float w = g_dinv[ed.x] * g_dinv[ed.y];
        float2 hs = *(const float2*)&g_tmp[ed.x * 64 + lane * 2];
        atomicAdd(&g_h[ed.y * 64 + lane * 2], w * hs.x);
        atomicAdd(&g_h[ed.y * 64 + lane * 2 + 1], w * hs.y);
    }
}

// -------- global mean pool (atomic accumulate from g_h); batch is int32 ----
__global__ void k_pool(const int* __restrict__ batch) {
    int idx = blockIdx.x * blockDim.x + threadIdx.x;
    if (idx >= N_NODES * 32) return;
    int v = idx >> 5, lane = idx & 31;
    int g = batch[v];
    if ((unsigned)g >= N_GRAPHS) return;
    float2 h = *(const float2*)&g_h[v * 64 + lane * 2];
    atomicAdd(&g_pool[g * 64 + lane * 2], h.x);
    atomicAdd(&g_pool[g * 64 + lane * 2 + 1], h.y);
    if (lane == 0) atomicAdd(&g_gcnt[g], 1);
}

// -------- head: mean, relu(g@W3+b3), @W4+b4 --------
__global__ void k_head(const float* __restrict__ W3, const float* __restrict__ b3,
                       const float* __restrict__ W4, const float* __restrict__ b4,
                       float* __restrict__ out) {
    int g = blockIdx.x;
    int j = threadIdx.x;   // 0..63
    __shared__ float mean[64];
    __shared__ float t[64];
    float c = (float)max(g_gcnt[g], 1);
    mean[j] = g_pool[g * 64 + j] / c;
    __syncthreads();
    float acc = 0.f;
    #pragma unroll
    for (int k = 0; k < 64; k++) acc += mean[k] * W3[k * 64 + j];
    t[j] = fmaxf(acc + b3[j], 0.f) * W4[j];
    __syncthreads();
    if (j < 32) {
        float v = t[j] + t[j + 32];
        #pragma unroll
        for (int s = 16; s > 0; s >>= 1) v += __shfl_down_sync(0xffffffffu, v, s);
        if (j == 0) out[g] = v + b4[0];
    }
}

extern "C" void kernel_launch(void* const* d_in, const int* in_sizes, int n_in,
                              void* d_out, int out_size) {
    const float* x     = (const float*)d_in[0];
    const int*   ei    = (const int*)d_in[1];     // int32 (JAX x64 disabled)
    const int*   batch = (const int*)d_in[2];     // int32
    const float* W1    = (const float*)d_in[3];
    const float* b1    = (const float*)d_in[4];
    const float* W2    = (const float*)d_in[5];
    const float* b2    = (const float*)d_in[6];
    const float* W3    = (const float*)d_in[7];
    const float* b3    = (const float*)d_in[8];
    const float* W4    = (const float*)d_in[9];
    const float* b4    = (const float*)d_in[10];
    float* out = (float*)d_out;

    k_init<<<(N_NODES + 255) / 256, 256>>>();
    k_build<<<(N_EDGES + 255) / 256, 256>>>(ei);
    k_dinv<<<(N_NODES + 255) / 256, 256>>>();

    // layer 1: g_tmp = x @ W1; g_h = Agg(g_tmp) + b1  (relu deferred to gemm2)
    k_gemm<false><<<N_NODES / 16, 256>>>(x, W1);
    k_agg<<<(N_NODES * 32 + 255) / 256, 256>>>(b1);
    k_ovf<<<4, 256>>>();

    // layer 2: g_tmp = relu(g_h) @ W2; g_h = Agg(g_tmp) + b2
    k_gemm<true><<<N_NODES / 16, 256>>>(nullptr, W2);
    k_agg<<<(N_NODES * 32 + 255) / 256, 256>>>(b2);
    k_ovf<<<4, 256>>>();

    // pool + head
    k_pool<<<(N_NODES * 32 + 255) / 256, 256>>>(batch);
    k_head<<<N_GRAPHS, 64>>>(W3, b3, W4, b4, out);
}

// round 4
// speedup vs baseline: 1.3069x; 1.3069x over previous
#include <cuda_runtime.h>
#include <cuda_bf16.h>

#define N_NODES 100000
#define N_EDGES 1600000
#define N_GRAPHS 512
#define DIM 64
#define CAP 64
#define OVF_CAP 8192
#define XPAD 68   // padded row stride for transposed X tile (16B-aligned, conflict-light)

// -------- scratch (device globals: no allocation allowed) --------
__device__ int   g_cnt[N_NODES];            // in-degree (real edges only)
__device__ int   g_col[N_NODES * CAP];      // ELL: sources per dst
__device__ float g_dinv[N_NODES];           // rsqrt(deg incl self-loop)
__device__ float g_tmp[N_NODES * DIM];      // GEMM output
__device__ float g_h[N_NODES * DIM];        // aggregation output
__device__ float g_pool[N_GRAPHS * DIM];
__device__ int   g_gcnt[N_GRAPHS];
__device__ int   g_novf;
__device__ int2  g_ovf[OVF_CAP];

// -------- init --------
__global__ void k_init() {
    int i = blockIdx.x * blockDim.x + threadIdx.x;
    if (i < N_NODES) g_cnt[i] = 0;
    if (i < N_GRAPHS * DIM) g_pool[i] = 0.f;
    if (i < N_GRAPHS) g_gcnt[i] = 0;
    if (i == 0) g_novf = 0;
}

// -------- build ELL adjacency (histogram + scatter in one pass) --------
__global__ void k_build(const int* __restrict__ ei) {
    int i = blockIdx.x * blockDim.x + threadIdx.x;
    if (i >= N_EDGES) return;
    int src = ei[i];
    int dst = ei[N_EDGES + i];
    if ((unsigned)src >= N_NODES || (unsigned)dst >= N_NODES) return;
    int pos = atomicAdd(&g_cnt[dst], 1);
    if (pos < CAP) {
        g_col[dst * CAP + pos] = src;
    } else {
        int o = atomicAdd(&g_novf, 1);
        if (o < OVF_CAP) g_ovf[o] = make_int2(src, dst);
    }
}

__global__ void k_dinv() {
    int i = blockIdx.x * blockDim.x + threadIdx.x;
    if (i < N_NODES) g_dinv[i] = rsqrtf((float)(g_cnt[i] + 1));
}

// -------- GEMM: g_tmp[N,64] = f(X)[N,64] @ W[64,64] --------
// 64 rows x 64 cols per block; 256 threads; 4x4 outputs per thread.
// X is staged TRANSPOSED in smem so the inner loop is 2x LDS.128 per 16 FMAs.
// FROM_H: read g_h (with relu) instead of the external X pointer.
template <bool FROM_H>
__global__ void __launch_bounds__(256) k_gemm(const float* __restrict__ X,
                                              const float* __restrict__ W) {
    __shared__ float Ws[64 * 64];        // Ws[k][c] row-major (as W)
    __shared__ float Xt[64 * XPAD];      // Xt[k][r] transposed, padded
    int t = threadIdx.x;
    int row0 = blockIdx.x * 64;

    #pragma unroll
    for (int i = t; i < 64 * 64; i += 256) Ws[i] = W[i];

    // load 64x64 X tile, store transposed
    #pragma unroll
    for (int i = t; i < 64 * 64; i += 256) {
        int r = i >> 6;          // local row
        int k = i & 63;          // feature
        int row = row0 + r;
        float v = 0.f;
        if (row < N_NODES) {
            int idx = row * 64 + k;
            v = FROM_H ? fmaxf(g_h[idx], 0.f) : X[idx];
        }
        Xt[k * XPAD + r] = v;
    }
    __syncthreads();

    int c    = (t & 15) * 4;     // col group: 0,4,...,60
    int rgrp = (t >> 4) * 4;     // row group: 0,4,...,60

    float4 a0 = make_float4(0.f, 0.f, 0.f, 0.f);
    float4 a1 = a0, a2 = a0, a3 = a0;
    #pragma unroll
    for (int k = 0; k < 64; k++) {
        const float4 w4 = *(const float4*)&Ws[k * 64 + c];
        const float4 x4 = *(const float4*)&Xt[k * XPAD + rgrp];
        a0.x += x4.x * w4.x; a0.y += x4.x * w4.y; a0.z += x4.x * w4.z; a0.w += x4.x * w4.w;
        a1.x += x4.y * w4.x; a1.y += x4.y * w4.y; a1.z += x4.y * w4.z; a1.w += x4.y * w4.w;
        a2.x += x4.z * w4.x; a2.y += x4.z * w4.y; a2.z += x4.z * w4.z; a2.w += x4.z * w4.w;
        a3.x += x4.w * w4.x; a3.y += x4.w * w4.y; a3.z += x4.w * w4.z; a3.w += x4.w * w4.w;
    }

    int row = row0 + rgrp;
    if (row + 0 < N_NODES) *(float4*)&g_tmp[(row + 0) * 64 + c] = a0;
    if (row + 1 < N_NODES) *(float4*)&g_tmp[(row + 1) * 64 + c] = a1;
    if (row + 2 < N_NODES) *(float4*)&g_tmp[(row + 2) * 64 + c] = a2;
    if (row + 3 < N_NODES) *(float4*)&g_tmp[(row + 3) * 64 + c] = a3;
}

// -------- aggregation: g_h = Agg(g_tmp) + bias; warp per dst node --------
__global__ void k_agg(const float* __restrict__ bias) {
    int warp = (blockIdx.x * blockDim.x + threadIdx.x) >> 5;
    int lane = threadIdx.x & 31;
    if (warp >= N_NODES) return;
    int v = warp;
    float dv = g_dinv[v];
    float2 hv = *(const float2*)&g_tmp[v * 64 + lane * 2];
    float2 acc;
    acc.x = dv * dv * hv.x;   // self-loop term
    acc.y = dv * dv * hv.y;
    int deg = g_cnt[v];
    if (deg > CAP) deg = CAP;
    const int* cols = &g_col[v * CAP];
    for (int base = 0; base < deg; base += 32) {
        int s = 0; float w = 0.f;
        if (base + lane < deg) {
            s = cols[base + lane];
            w = g_dinv[s] * dv;
        }
        int m = min(32, deg - base);
        for (int j = 0; j < m; j++) {
            int   sj = __shfl_sync(0xffffffffu, s, j);
            float wj = __shfl_sync(0xffffffffu, w, j);
            float2 hs = *(const float2*)&g_tmp[sj * 64 + lane * 2];
            acc.x += wj * hs.x;
            acc.y += wj * hs.y;
        }
    }
    float2 b = *(const float2*)&bias[lane * 2];
    acc.x += b.x;
    acc.y += b.y;
    *(float2*)&g_h[v * 64 + lane * 2] = acc;
}

// -------- overflow edges (normally zero) — atomic fallback into g_h --------
__global__ void k_ovf() {
    int n = g_novf;
    if (n > OVF_CAP) n = OVF_CAP;
    for (int idx = blockIdx.x * blockDim.x + threadIdx.x; idx < n * 32;
         idx += gridDim.x * blockDim.x) {
        int e = idx >> 5, lane = idx & 31;
        int2 ed = g_ovf[e];
        float w = g_dinv[ed.x] * g_dinv[ed.y];
        float2 hs = *(const float2*)&g_tmp[ed.x * 64 + lane * 2];
        atomicAdd(&g_h[ed.y * 64 + lane * 2], w * hs.x);
        atomicAdd(&g_h[ed.y * 64 + lane * 2 + 1], w * hs.y);
    }
}

// -------- global mean pool (atomic accumulate from g_h) --------
__global__ void k_pool(const int* __restrict__ batch) {
    int idx = blockIdx.x * blockDim.x + threadIdx.x;
    if (idx >= N_NODES * 32) return;
    int v = idx >> 5, lane = idx & 31;
    int g = batch[v];
    if ((unsigned)g >= N_GRAPHS) return;
    float2 h = *(const float2*)&g_h[v * 64 + lane * 2];
    atomicAdd(&g_pool[g * 64 + lane * 2], h.x);
    atomicAdd(&g_pool[g * 64 + lane * 2 + 1], h.y);
    if (lane == 0) atomicAdd(&g_gcnt[g], 1);
}

// -------- head: mean, relu(g@W3+b3), @W4+b4 --------
__global__ void k_head(const float* __restrict__ W3, const float* __restrict__ b3,
                       const float* __restrict__ W4, const float* __restrict__ b4,
                       float* __restrict__ out) {
    int g = blockIdx.x;
    int j = threadIdx.x;   // 0..63
    __shared__ float mean[64];
    __shared__ float t[64];
    float c = (float)max(g_gcnt[g], 1);
    mean[j] = g_pool[g * 64 + j] / c;
    __syncthreads();
    float acc = 0.f;
    #pragma unroll
    for (int k = 0; k < 64; k++) acc += mean[k] * W3[k * 64 + j];
    t[j] = fmaxf(acc + b3[j], 0.f) * W4[j];
    __syncthreads();
    if (j < 32) {
        float v = t[j] + t[j + 32];
        #pragma unroll
        for (int s = 16; s > 0; s >>= 1) v += __shfl_down_sync(0xffffffffu, v, s);
        if (j == 0) out[g] = v + b4[0];
    }
}

extern "C" void kernel_launch(void* const* d_in, const int* in_sizes, int n_in,
                              void* d_out, int out_size) {
    const float* x     = (const float*)d_in[0];
    const int*   ei    = (const int*)d_in[1];     // int32
    const int*   batch = (const int*)d_in[2];     // int32
    const float* W1    = (const float*)d_in[3];
    const float* b1    = (const float*)d_in[4];
    const float* W2    = (const float*)d_in[5];
    const float* b2    = (const float*)d_in[6];
    const float* W3    = (const float*)d_in[7];
    const float* b3    = (const float*)d_in[8];
    const float* W4    = (const float*)d_in[9];
    const float* b4    = (const float*)d_in[10];
    float* out = (float*)d_out;

    const int GEMM_BLOCKS = (N_NODES + 63) / 64;

    k_init<<<(N_NODES + 255) / 256, 256>>>();
    k_build<<<(N_EDGES + 255) / 256, 256>>>(ei);
    k_dinv<<<(N_NODES + 255) / 256, 256>>>();

    // layer 1: g_tmp = x @ W1; g_h = Agg(g_tmp) + b1  (relu deferred to gemm2)
    k_gemm<false><<<GEMM_BLOCKS, 256>>>(x, W1);
    k_agg<<<(N_NODES * 32 + 255) / 256, 256>>>(b1);
    k_ovf<<<4, 256>>>();

    // layer 2: g_tmp = relu(g_h) @ W2; g_h = Agg(g_tmp) + b2
    k_gemm<true><<<GEMM_BLOCKS, 256>>>(nullptr, W2);
    k_agg<<<(N_NODES * 32 + 255) / 256, 256>>>(b2);
    k_ovf<<<4, 256>>>();

    // pool + head
    k_pool<<<(N_NODES * 32 + 255) / 256, 256>>>(batch);
    k_head<<<N_GRAPHS, 64>>>(W3, b3, W4, b4, out);
}

// round 5
// speedup vs baseline: 1.4260x; 1.0911x over previous
#include <cuda_runtime.h>
#include <cuda_bf16.h>
#include <cuda_fp16.h>

#define N_NODES 100000
#define N_EDGES 1600000
#define N_GRAPHS 512
#define DIM 64
#define CAP 64
#define OVF_CAP 8192
#define XPAD 68

// -------- scratch (device globals: no allocation allowed) --------
__device__ int     g_cnt[N_NODES];          // in-degree (real edges only)
__device__ int     g_col[N_NODES * CAP];    // ELL: sources per dst
__device__ float   g_dinv[N_NODES];         // rsqrt(deg incl self-loop)
__device__ float   g_tmp[N_NODES * DIM];    // GEMM output (fp32, unscaled)
__device__ __half2 g_tmp_h[N_NODES * 32];   // GEMM output * dinv[row], fp16 (gather copy)
__device__ float   g_h[N_NODES * DIM];      // layer-1 aggregation output
__device__ float   g_pool[N_GRAPHS * DIM];
__device__ int     g_gcnt[N_GRAPHS];
__device__ int     g_novf;
__device__ int2    g_ovf[OVF_CAP];

// -------- init --------
__global__ void k_init() {
    int i = blockIdx.x * blockDim.x + threadIdx.x;
    if (i < N_NODES) g_cnt[i] = 0;
    if (i < N_GRAPHS * DIM) g_pool[i] = 0.f;
    if (i < N_GRAPHS) g_gcnt[i] = 0;
    if (i == 0) g_novf = 0;
}

// -------- build ELL adjacency --------
__global__ void k_build(const int* __restrict__ ei) {
    int i = blockIdx.x * blockDim.x + threadIdx.x;
    if (i >= N_EDGES) return;
    int src = ei[i];
    int dst = ei[N_EDGES + i];
    if ((unsigned)src >= N_NODES || (unsigned)dst >= N_NODES) return;
    int pos = atomicAdd(&g_cnt[dst], 1);
    if (pos < CAP) {
        g_col[dst * CAP + pos] = src;
    } else {
        int o = atomicAdd(&g_novf, 1);
        if (o < OVF_CAP) g_ovf[o] = make_int2(src, dst);
    }
}

// -------- dinv + per-graph node counts --------
__global__ void k_dinv(const int* __restrict__ batch) {
    int i = blockIdx.x * blockDim.x + threadIdx.x;
    if (i >= N_NODES) return;
    g_dinv[i] = rsqrtf((float)(g_cnt[i] + 1));
    int g = batch[i];
    if ((unsigned)g < N_GRAPHS) atomicAdd(&g_gcnt[g], 1);
}

// -------- GEMM: g_tmp = f(X) @ W ; g_tmp_h = (g_tmp * dinv[row]) as fp16 ----
template <bool FROM_H>
__global__ void __launch_bounds__(256) k_gemm(const float* __restrict__ X,
                                              const float* __restrict__ W) {
    __shared__ float Ws[64 * 64];
    __shared__ float Xt[64 * XPAD];
    int t = threadIdx.x;
    int row0 = blockIdx.x * 64;

    #pragma unroll
    for (int i = t; i < 64 * 64; i += 256) Ws[i] = W[i];
    #pragma unroll
    for (int i = t; i < 64 * 64; i += 256) {
        int r = i >> 6, k = i & 63;
        int row = row0 + r;
        float v = 0.f;
        if (row < N_NODES) {
            int idx = row * 64 + k;
            v = FROM_H ? fmaxf(g_h[idx], 0.f) : X[idx];
        }
        Xt[k * XPAD + r] = v;
    }
    __syncthreads();

    int c    = (t & 15) * 4;
    int rgrp = (t >> 4) * 4;

    float4 a0 = make_float4(0.f, 0.f, 0.f, 0.f);
    float4 a1 = a0, a2 = a0, a3 = a0;
    #pragma unroll
    for (int k = 0; k < 64; k++) {
        const float4 w4 = *(const float4*)&Ws[k * 64 + c];
        const float4 x4 = *(const float4*)&Xt[k * XPAD + rgrp];
        a0.x += x4.x * w4.x; a0.y += x4.x * w4.y; a0.z += x4.x * w4.z; a0.w += x4.x * w4.w;
        a1.x += x4.y * w4.x; a1.y += x4.y * w4.y; a1.z += x4.y * w4.z; a1.w += x4.y * w4.w;
        a2.x += x4.z * w4.x; a2.y += x4.z * w4.y; a2.z += x4.z * w4.z; a2.w += x4.z * w4.w;
        a3.x += x4.w * w4.x; a3.y += x4.w * w4.y; a3.z += x4.w * w4.z; a3.w += x4.w * w4.w;
    }

    int row = row0 + rgrp;
    #pragma unroll
    for (int i = 0; i < 4; i++) {
        float4 a = (i == 0) ? a0 : (i == 1) ? a1 : (i == 2) ? a2 : a3;
        int rr = row + i;
        if (rr < N_NODES) {
            *(float4*)&g_tmp[rr * 64 + c] = a;
            float s = g_dinv[rr];
            __half2 p0 = __floats2half2_rn(a.x * s, a.y * s);
            __half2 p1 = __floats2half2_rn(a.z * s, a.w * s);
            __half2* dst = &g_tmp_h[rr * 32 + (c >> 1)];
            dst[0] = p0;
            dst[1] = p1;
        }
    }
}

// -------- aggregation: warp per dst node; gathers pre-scaled fp16 rows ----
// TO_POOL: layer 2 — accumulate directly into g_pool (bias added in head).
template <bool TO_POOL>
__global__ void __launch_bounds__(256) k_agg(const float* __restrict__ bias,
                                             const int* __restrict__ batch) {
    int warp = (blockIdx.x * blockDim.x + threadIdx.x) >> 5;
    int lane = threadIdx.x & 31;
    if (warp >= N_NODES) return;
    int v = warp;
    float dv = g_dinv[v];

    float2 accn = make_float2(0.f, 0.f);   // sum of dinv[s]*h[s]
    int deg = g_cnt[v];
    if (deg > CAP) deg = CAP;
    const int* cols = &g_col[v * CAP];
    for (int base = 0; base < deg; base += 32) {
        int s = (base + lane < deg) ? cols[base + lane] : 0;
        int m = min(32, deg - base);
        int j = 0;
        for (; j + 4 <= m; j += 4) {
            int s0 = __shfl_sync(0xffffffffu, s, j);
            int s1 = __shfl_sync(0xffffffffu, s, j + 1);
            int s2 = __shfl_sync(0xffffffffu, s, j + 2);
            int s3 = __shfl_sync(0xffffffffu, s, j + 3);
            __half2 h0 = g_tmp_h[s0 * 32 + lane];
            __half2 h1 = g_tmp_h[s1 * 32 + lane];
            __half2 h2 = g_tmp_h[s2 * 32 + lane];
            __half2 h3 = g_tmp_h[s3 * 32 + lane];
            float2 f0 = __half22float2(h0);
            float2 f1 = __half22float2(h1);
            float2 f2 = __half22float2(h2);
            float2 f3 = __half22float2(h3);
            accn.x += (f0.x + f1.x) + (f2.x + f3.x);
            accn.y += (f0.y + f1.y) + (f2.y + f3.y);
        }
        for (; j < m; j++) {
            int sj = __shfl_sync(0xffffffffu, s, j);
            float2 f = __half22float2(g_tmp_h[sj * 32 + lane]);
            accn.x += f.x;
            accn.y += f.y;
        }
    }

    float2 own = *(const float2*)&g_tmp[v * 64 + lane * 2];
    float2 acc;
    acc.x = dv * dv * own.x + dv * accn.x;
    acc.y = dv * dv * own.y + dv * accn.y;

    if (TO_POOL) {
        int g = batch[v];
        if ((unsigned)g < N_GRAPHS) {
            atomicAdd(&g_pool[g * 64 + lane * 2], acc.x);
            atomicAdd(&g_pool[g * 64 + lane * 2 + 1], acc.y);
        }
    } else {
        float2 b = *(const float2*)&bias[lane * 2];
        acc.x += b.x;
        acc.y += b.y;
        *(float2*)&g_h[v * 64 + lane * 2] = acc;
    }
}

// -------- overflow edges (normally zero) — exact fp32 fallback --------
template <bool TO_POOL>
__global__ void k_ovf(const int* __restrict__ batch) {
    int n = g_novf;
    if (n > OVF_CAP) n = OVF_CAP;
    for (int idx = blockIdx.x * blockDim.x + threadIdx.x; idx < n * 32;
         idx += gridDim.x * blockDim.x) {
        int e = idx >> 5, lane = idx & 31;
        int2 ed = g_ovf[e];
        float w = g_dinv[ed.x] * g_dinv[ed.y];
        float2 hs = *(const float2*)&g_tmp[ed.x * 64 + lane * 2];
        if (TO_POOL) {
            int g = batch[ed.y];
            if ((unsigned)g < N_GRAPHS) {
                atomicAdd(&g_pool[g * 64 + lane * 2], w * hs.x);
                atomicAdd(&g_pool[g * 64 + lane * 2 + 1], w * hs.y);
            }
        } else {
            atomicAdd(&g_h[ed.y * 64 + lane * 2], w * hs.x);
            atomicAdd(&g_h[ed.y * 64 + lane * 2 + 1], w * hs.y);
        }
    }
}

// -------- head: mean = pool/cnt + b2; relu(mean@W3+b3) @ W4 + b4 --------
__global__ void k_head(const float* __restrict__ b2,
                       const float* __restrict__ W3, const float* __restrict__ b3,
                       const float* __restrict__ W4, const float* __restrict__ b4,
                       float* __restrict__ out) {
    int g = blockIdx.x;
    int j = threadIdx.x;   // 0..63
    __shared__ float mean[64];
    __shared__ float t[64];
    float c = (float)max(g_gcnt[g], 1);
    mean[j] = g_pool[g * 64 + j] / c + b2[j];
    __syncthreads();
    float acc = 0.f;
    #pragma unroll
    for (int k = 0; k < 64; k++) acc += mean[k] * W3[k * 64 + j];
    t[j] = fmaxf(acc + b3[j], 0.f) * W4[j];
    __syncthreads();
    if (j < 32) {
        float v = t[j] + t[j + 32];
        #pragma unroll
        for (int s = 16; s > 0; s >>= 1) v += __shfl_down_sync(0xffffffffu, v, s);
        if (j == 0) out[g] = v + b4[0];
    }
}

extern "C" void kernel_launch(void* const* d_in, const int* in_sizes, int n_in,
                              void* d_out, int out_size) {
    const float* x     = (const float*)d_in[0];
    const int*   ei    = (const int*)d_in[1];     // int32
    const int*   batch = (const int*)d_in[2];     // int32
    const float* W1    = (const float*)d_in[3];
    const float* b1    = (const float*)d_in[4];
    const float* W2    = (const float*)d_in[5];
    const float* b2    = (const float*)d_in[6];
    const float* W3    = (const float*)d_in[7];
    const float* b3    = (const float*)d_in[8];
    const float* W4    = (const float*)d_in[9];
    const float* b4    = (const float*)d_in[10];
    float* out = (float*)d_out;

    const int GEMM_BLOCKS = (N_NODES + 63) / 64;
    const int AGG_BLOCKS  = (N_NODES * 32 + 255) / 256;

    k_init<<<(N_NODES + 255) / 256, 256>>>();
    k_build<<<(N_EDGES + 255) / 256, 256>>>(ei);
    k_dinv<<<(N_NODES + 255) / 256, 256>>>(batch);

    // layer 1: g_tmp = x @ W1 (+fp16 scaled copy); g_h = Agg + b1
    k_gemm<false><<<GEMM_BLOCKS, 256>>>(x, W1);
    k_agg<false><<<AGG_BLOCKS, 256>>>(b1, batch);
    k_ovf<false><<<4, 256>>>(batch);

    // layer 2: g_tmp = relu(g_h) @ W2; Agg accumulates straight into g_pool
    k_gemm<true><<<GEMM_BLOCKS, 256>>>(nullptr, W2);
    k_agg<true><<<AGG_BLOCKS, 256>>>(nullptr, batch);
    k_ovf<true><<<4, 256>>>(batch);

    // head (adds b2 to the mean)
    k_head<<<N_GRAPHS, 64>>>(b2, W3, b3, W4, b4, out);
}

// round 7
// speedup vs baseline: 1.6563x; 1.1615x over previous
#include <cuda_runtime.h>
#include <cuda_bf16.h>
#include <cuda_fp16.h>
#include <cstdint>

#define N_NODES 100000
#define N_EDGES 1600000
#define N_GRAPHS 512
#define DIM 64
#define CAP 64
#define OVF_CAP 8192
#define XS_PAD 72   // halves per row in smem staging (conflict-free fragments)

// -------- scratch (device globals) --------
__device__ int     g_cnt[N_NODES];
__device__ int     g_col[N_NODES * CAP];
__device__ float   g_dinv[N_NODES];
__device__ __half2 g_tmp_h[N_NODES * 32];   // h[row]*dinv[row], fp16
__device__ float   g_h[N_NODES * DIM];      // layer-1 agg output (fp32)
__device__ float   g_pool[N_GRAPHS * DIM];
__device__ int     g_gcnt[N_GRAPHS];
__device__ int     g_novf;
__device__ int2    g_ovf[OVF_CAP];

__global__ void k_init() {
    int i = blockIdx.x * blockDim.x + threadIdx.x;
    if (i < N_GRAPHS * DIM) g_pool[i] = 0.f;
    if (i < N_GRAPHS) g_gcnt[i] = 0;
    if (i < N_NODES) g_cnt[i] = 0;
    if (i == 0) g_novf = 0;
}

// -------- build ELL adjacency; 4 edges per thread --------
__global__ void k_build(const int* __restrict__ ei) {
    int i4 = blockIdx.x * blockDim.x + threadIdx.x;
    if (i4 >= N_EDGES / 4) return;
    int4 s4 = ((const int4*)ei)[i4];
    int4 d4 = ((const int4*)(ei + N_EDGES))[i4];
    int ss[4] = {s4.x, s4.y, s4.z, s4.w};
    int dd[4] = {d4.x, d4.y, d4.z, d4.w};
    #pragma unroll
    for (int k = 0; k < 4; k++) {
        int src = ss[k], dst = dd[k];
        if ((unsigned)src >= N_NODES || (unsigned)dst >= N_NODES) continue;
        int pos = atomicAdd(&g_cnt[dst], 1);
        if (pos < CAP) {
            g_col[dst * CAP + pos] = src;
        } else {
            int o = atomicAdd(&g_novf, 1);
            if (o < OVF_CAP) g_ovf[o] = make_int2(src, dst);
        }
    }
}

__global__ void k_dinv(const int* __restrict__ batch) {
    int i = blockIdx.x * blockDim.x + threadIdx.x;
    if (i >= N_NODES) return;
    g_dinv[i] = rsqrtf((float)(g_cnt[i] + 1));
    int g = batch[i];
    if ((unsigned)g < N_GRAPHS) atomicAdd(&g_gcnt[g], 1);
}

// -------- tensor-core GEMM: g_tmp_h = (f(X) @ W) * dinv[row], fp16 out ----
// 128 rows x 64 cols per block, 256 threads (8 warps), warp = 16x64 strip.
// mma.sync.m16n8k16 f16*f16 -> f32.
template <bool FROM_H>
__global__ void __launch_bounds__(256) k_gemm(const float* __restrict__ X,
                                              const float* __restrict__ W) {
    __shared__ __half Xs[128 * XS_PAD];   // Xs[r][k], fp16, padded
    __shared__ __half Wt[64 * XS_PAD];    // Wt[n][k] = W[k][n], fp16, padded
    int t = threadIdx.x;
    int lane = t & 31;
    int w = t >> 5;                        // warp 0..7
    int row0 = blockIdx.x * 128;

    // stage W transposed -> Wt[n][k]
    for (int i = t; i < 64 * 64; i += 256) {
        int k = i >> 6, n = i & 63;
        Wt[n * XS_PAD + k] = __float2half_rn(W[i]);
    }
    // stage X tile -> Xs[r][k] (fp16), zero-pad OOB rows
    for (int i = t; i < 128 * 16; i += 256) {       // 16 float4 per row
        int r = i >> 4, q = (i & 15) * 4;
        int row = row0 + r;
        float4 v = make_float4(0.f, 0.f, 0.f, 0.f);
        if (row < N_NODES) {
            if (FROM_H) {
                const float4 hv = *(const float4*)&g_h[row * 64 + q];
                v.x = fmaxf(hv.x, 0.f); v.y = fmaxf(hv.y, 0.f);
                v.z = fmaxf(hv.z, 0.f); v.w = fmaxf(hv.w, 0.f);
            } else {
                v = *(const float4*)&X[row * 64 + q];
            }
        }
        __half2* p = (__half2*)&Xs[r * XS_PAD + q];
        p[0] = __floats2half2_rn(v.x, v.y);
        p[1] = __floats2half2_rn(v.z, v.w);
    }
    __syncthreads();

    int grp = lane >> 2;        // 0..7
    int qid = lane & 3;         // 0..3
    int arow = w * 16 + grp;    // local A row for a0/a2

    float c[8][4];
    #pragma unroll
    for (int n = 0; n < 8; n++)
        #pragma unroll
        for (int j = 0; j < 4; j++) c[n][j] = 0.f;

    #pragma unroll
    for (int kk = 0; kk < 4; kk++) {
        int k0 = kk * 16 + qid * 2;
        uint32_t a0 = *(const uint32_t*)&Xs[(arow)     * XS_PAD + k0];
        uint32_t a1 = *(const uint32_t*)&Xs[(arow + 8) * XS_PAD + k0];
        uint32_t a2 = *(const uint32_t*)&Xs[(arow)     * XS_PAD + k0 + 8];
        uint32_t a3 = *(const uint32_t*)&Xs[(arow + 8) * XS_PAD + k0 + 8];
        #pragma unroll
        for (int n = 0; n < 8; n++) {
            int nc = n * 8 + grp;
            uint32_t b0 = *(const uint32_t*)&Wt[nc * XS_PAD + k0];
            uint32_t b1 = *(const uint32_t*)&Wt[nc * XS_PAD + k0 + 8];
            asm volatile(
                "mma.sync.aligned.m16n8k16.row.col.f32.f16.f16.f32 "
                "{%0,%1,%2,%3}, {%4,%5,%6,%7}, {%8,%9}, {%0,%1,%2,%3};"
                : "+f"(c[n][0]), "+f"(c[n][1]), "+f"(c[n][2]), "+f"(c[n][3])
                : "r"(a0), "r"(a1), "r"(a2), "r"(a3), "r"(b0), "r"(b1));
        }
    }

    // epilogue: scale by dinv[row], pack fp16, store
    int r0 = row0 + w * 16 + grp;
    int r1 = r0 + 8;
    float dv0 = (r0 < N_NODES) ? g_dinv[r0] : 0.f;
    float dv1 = (r1 < N_NODES) ? g_dinv[r1] : 0.f;
    #pragma unroll
    for (int n = 0; n < 8; n++) {
        int cw = n * 4 + qid;   // half2 index within the 32-wide row
        if (r0 < N_NODES)
            g_tmp_h[r0 * 32 + cw] = __floats2half2_rn(c[n][0] * dv0, c[n][1] * dv0);
        if (r1 < N_NODES)
            g_tmp_h[r1 * 32 + cw] = __floats2half2_rn(c[n][2] * dv1, c[n][3] * dv1);
    }
}

// -------- aggregation: warp per dst; gathers pre-scaled fp16 rows --------
template <bool TO_POOL>
__global__ void __launch_bounds__(256) k_agg(const float* __restrict__ bias,
                                             const int* __restrict__ batch) {
    int warp = (blockIdx.x * blockDim.x + threadIdx.x) >> 5;
    int lane = threadIdx.x & 31;
    if (warp >= N_NODES) return;
    int v = warp;
    float dv = g_dinv[v];

    float2 own = __half22float2(g_tmp_h[v * 32 + lane]);  // = dv * h_v
    float2 accn = own;                                    // self-loop term (dv*h_v)
    int deg = g_cnt[v];
    if (deg > CAP) deg = CAP;
    const int* cols = &g_col[v * CAP];
    for (int base = 0; base < deg; base += 32) {
        int s = (base + lane < deg) ? cols[base + lane] : 0;
        int m = min(32, deg - base);
        int j = 0;
        for (; j + 4 <= m; j += 4) {
            int s0 = __shfl_sync(0xffffffffu, s, j);
            int s1 = __shfl_sync(0xffffffffu, s, j + 1);
            int s2 = __shfl_sync(0xffffffffu, s, j + 2);
            int s3 = __shfl_sync(0xffffffffu, s, j + 3);
            float2 f0 = __half22float2(g_tmp_h[s0 * 32 + lane]);
            float2 f1 = __half22float2(g_tmp_h[s1 * 32 + lane]);
            float2 f2 = __half22float2(g_tmp_h[s2 * 32 + lane]);
            float2 f3 = __half22float2(g_tmp_h[s3 * 32 + lane]);
            accn.x += (f0.x + f1.x) + (f2.x + f3.x);
            accn.y += (f0.y + f1.y) + (f2.y + f3.y);
        }
        for (; j < m; j++) {
            int sj = __shfl_sync(0xffffffffu, s, j);
            float2 f = __half22float2(g_tmp_h[sj * 32 + lane]);
            accn.x += f.x;
            accn.y += f.y;
        }
    }

    float2 acc;
    acc.x = dv * accn.x;
    acc.y = dv * accn.y;

    if (TO_POOL) {
        int g = batch[v];
        if ((unsigned)g < N_GRAPHS) {
            atomicAdd(&g_pool[g * 64 + lane * 2], acc.x);
            atomicAdd(&g_pool[g * 64 + lane * 2 + 1], acc.y);
        }
    } else {
        float2 b = *(const float2*)&bias[lane * 2];
        acc.x += b.x;
        acc.y += b.y;
        *(float2*)&g_h[v * 64 + lane * 2] = acc;
    }
}

// -------- overflow edges (normally zero) --------
template <bool TO_POOL>
__global__ void k_ovf(const int* __restrict__ batch) {
    int n = g_novf;
    if (n > OVF_CAP) n = OVF_CAP;
    for (int idx = blockIdx.x * blockDim.x + threadIdx.x; idx < n * 32;
         idx += gridDim.x * blockDim.x) {
        int e = idx >> 5, lane = idx & 31;
        int2 ed = g_ovf[e];
        float w = g_dinv[ed.y];                                 // src dinv is pre-baked
        float2 hs = __half22float2(g_tmp_h[ed.x * 32 + lane]);
        if (TO_POOL) {
            int g = batch[ed.y];
            if ((unsigned)g < N_GRAPHS) {
                atomicAdd(&g_pool[g * 64 + lane * 2], w * hs.x);
                atomicAdd(&g_pool[g * 64 + lane * 2 + 1], w * hs.y);
            }
        } else {
            atomicAdd(&g_h[ed.y * 64 + lane * 2], w * hs.x);
            atomicAdd(&g_h[ed.y * 64 + lane * 2 + 1], w * hs.y);
        }
    }
}

// -------- head: mean = pool/cnt + b2; relu(mean@W3+b3) @ W4 + b4 --------
__global__ void k_head(const float* __restrict__ b2,
                       const float* __restrict__ W3, const float* __restrict__ b3,
                       const float* __restrict__ W4, const float* __restrict__ b4,
                       float* __restrict__ out) {
    int g = blockIdx.x;
    int j = threadIdx.x;
    __shared__ float mean[64];
    __shared__ float t[64];
    float c = (float)max(g_gcnt[g], 1);
    mean[j] = g_pool[g * 64 + j] / c + b2[j];
    __syncthreads();
    float acc = 0.f;
    #pragma unroll
    for (int k = 0; k < 64; k++) acc += mean[k] * W3[k * 64 + j];
    t[j] = fmaxf(acc + b3[j], 0.f) * W4[j];
    __syncthreads();
    if (j < 32) {
        float v = t[j] + t[j + 32];
        #pragma unroll
        for (int s = 16; s > 0; s >>= 1) v += __shfl_down_sync(0xffffffffu, v, s);
        if (j == 0) out[g] = v + b4[0];
    }
}

extern "C" void kernel_launch(void* const* d_in, const int* in_sizes, int n_in,
                              void* d_out, int out_size) {
    const float* x     = (const float*)d_in[0];
    const int*   ei    = (const int*)d_in[1];
    const int*   batch = (const int*)d_in[2];
    const float* W1    = (const float*)d_in[3];
    const float* b1    = (const float*)d_in[4];
    const float* W2    = (const float*)d_in[5];
    const float* b2    = (const float*)d_in[6];
    const float* W3    = (const float*)d_in[7];
    const float* b3    = (const float*)d_in[8];
    const float* W4    = (const float*)d_in[9];
    const float* b4    = (const float*)d_in[10];
    float* out = (float*)d_out;

    const int GEMM_BLOCKS = (N_NODES + 127) / 128;
    const int AGG_BLOCKS  = (N_NODES * 32 + 255) / 256;

    int init_blocks = (N_GRAPHS * DIM + 255) / 256 > (N_NODES + 255) / 256
                          ? (N_GRAPHS * DIM + 255) / 256
                          : (N_NODES + 255) / 256;
    k_init<<<init_blocks, 256>>>();
    k_build<<<(N_EDGES / 4 + 255) / 256, 256>>>(ei);
    k_dinv<<<(N_NODES + 255) / 256, 256>>>(batch);

    // layer 1
    k_gemm<false><<<GEMM_BLOCKS, 256>>>(x, W1);
    k_agg<false><<<AGG_BLOCKS, 256>>>(b1, batch);
    k_ovf<false><<<4, 256>>>(batch);

    // layer 2 (agg accumulates straight into g_pool)
    k_gemm<true><<<GEMM_BLOCKS, 256>>>(nullptr, W2);
    k_agg<true><<<AGG_BLOCKS, 256>>>(nullptr, batch);
    k_ovf<true><<<4, 256>>>(batch);

    k_head<<<N_GRAPHS, 64>>>(b2, W3, b3, W4, b4, out);
}

// round 8
// speedup vs baseline: 1.7605x; 1.0629x over previous
#include <cuda_runtime.h>
#include <cuda_bf16.h>
#include <cuda_fp16.h>
#include <cstdint>

#define N_NODES 100000
#define N_EDGES 1600000
#define N_GRAPHS 512
#define DIM 64
#define CAP 64
#define OVF_CAP 8192

// -------- scratch (device globals) --------
__device__ int     g_cnt[N_NODES];
__device__ int     g_col[N_NODES * CAP];
__device__ float   g_dinv[N_NODES];
__device__ __half2 g_tmp_h[N_NODES * 32];   // h[row]*dinv[row], fp16 (gather rows)
__device__ __half2 g_h_h[N_NODES * 32];     // layer-1 agg output (+b1), fp16
__device__ float   g_pool[N_GRAPHS * DIM];
__device__ int     g_gcnt[N_GRAPHS];
__device__ int     g_novf;
__device__ int2    g_ovf[OVF_CAP];

__device__ __forceinline__ void cp_async16(uint32_t daddr, const void* src, int nbytes) {
    asm volatile("cp.async.ca.shared.global [%0], [%1], 16, %2;"
                 :: "r"(daddr), "l"(src), "r"(nbytes));
}

__global__ void k_init() {
    int i = blockIdx.x * blockDim.x + threadIdx.x;
    if (i < N_GRAPHS * DIM) g_pool[i] = 0.f;
    if (i < N_GRAPHS) g_gcnt[i] = 0;
    if (i < N_NODES) g_cnt[i] = 0;
    if (i == 0) g_novf = 0;
}

// -------- build ELL adjacency; 4 edges per thread --------
__global__ void k_build(const int* __restrict__ ei) {
    int i4 = blockIdx.x * blockDim.x + threadIdx.x;
    if (i4 >= N_EDGES / 4) return;
    int4 s4 = ((const int4*)ei)[i4];
    int4 d4 = ((const int4*)(ei + N_EDGES))[i4];
    int ss[4] = {s4.x, s4.y, s4.z, s4.w};
    int dd[4] = {d4.x, d4.y, d4.z, d4.w};
    #pragma unroll
    for (int k = 0; k < 4; k++) {
        int src = ss[k], dst = dd[k];
        if ((unsigned)src >= N_NODES || (unsigned)dst >= N_NODES) continue;
        int pos = atomicAdd(&g_cnt[dst], 1);
        if (pos < CAP) {
            g_col[dst * CAP + pos] = src;
        } else {
            int o = atomicAdd(&g_novf, 1);
            if (o < OVF_CAP) g_ovf[o] = make_int2(src, dst);
        }
    }
}

__global__ void k_dinv(const int* __restrict__ batch) {
    int i = blockIdx.x * blockDim.x + threadIdx.x;
    if (i >= N_NODES) return;
    g_dinv[i] = rsqrtf((float)(g_cnt[i] + 1));
    int g = batch[i];
    if ((unsigned)g < N_GRAPHS) atomicAdd(&g_gcnt[g], 1);
}

// -------- tensor-core GEMM: g_tmp_h = (f(X) @ W) * dinv[row], fp16 out ----
// 128 rows x 64 cols per block, 8 warps, warp = 16x64 strip, mma m16n8k16.
// X staged via cp.async (fp32 for layer1, fp16 g_h_h for layer2; relu via hmax2).
template <bool FROM_H>
__global__ void __launch_bounds__(256) k_gemm(const float* __restrict__ X,
                                              const float* __restrict__ W) {
    constexpr int PADH = 80;  // halves per row (fp16 path), 160B: 16B-aligned
    constexpr int PADF = 72;  // floats per row (fp32 path), 288B: 16B-aligned
    __shared__ __align__(16) unsigned char Xraw[FROM_H ? (128 * PADH * 2)
                                                       : (128 * PADF * 4)];
    __shared__ __half Wt[64 * 72];   // Wt[n][k] = W[k][n]
    int t = threadIdx.x;
    int lane = t & 31;
    int w = t >> 5;
    int row0 = blockIdx.x * 128;
    uint32_t xbase = (uint32_t)__cvta_generic_to_shared(Xraw);

    // 1) fire all X cp.asyncs (no register dependency, deep MLP)
    if (FROM_H) {
        for (int i = t; i < 128 * 8; i += 256) {          // 8 x 16B per 128B row
            int r = i >> 3, ch = i & 7;
            int row = row0 + r;
            int rc = row < N_NODES ? row : 0;
            const char* src = (const char*)g_h_h + (size_t)rc * 128 + ch * 16;
            cp_async16(xbase + (uint32_t)(r * PADH + ch * 8) * 2, src,
                       row < N_NODES ? 16 : 0);
        }
    } else {
        for (int i = t; i < 128 * 16; i += 256) {         // 16 x 16B per 256B row
            int r = i >> 4, ch = i & 15;
            int row = row0 + r;
            int rc = row < N_NODES ? row : 0;
            const char* src = (const char*)X + (size_t)rc * 256 + ch * 16;
            cp_async16(xbase + (uint32_t)(r * PADF + ch * 4) * 4, src,
                       row < N_NODES ? 16 : 0);
        }
    }
    // 2) W transpose-convert overlaps with in-flight cp.asyncs
    for (int i = t; i < 64 * 64; i += 256) {
        int k = i >> 6, n = i & 63;
        Wt[n * 72 + k] = __float2half_rn(W[i]);
    }
    asm volatile("cp.async.commit_group;");
    asm volatile("cp.async.wait_group 0;");
    __syncthreads();

    int grp = lane >> 2;
    int qid = lane & 3;
    int arow = w * 16 + grp;
    const __half* Xh = (const __half*)Xraw;
    const float*  Xf = (const float*)Xraw;
    const __half2 z2 = __float2half2_rn(0.f);

    float c[8][4];
    #pragma unroll
    for (int n = 0; n < 8; n++)
        #pragma unroll
        for (int j = 0; j < 4; j++) c[n][j] = 0.f;

    #pragma unroll
    for (int kk = 0; kk < 4; kk++) {
        int k0 = kk * 16 + qid * 2;
        uint32_t a0, a1, a2, a3;
        if (FROM_H) {
            __half2 v0 = __hmax2(*(const __half2*)&Xh[(arow)     * PADH + k0], z2);
            __half2 v1 = __hmax2(*(const __half2*)&Xh[(arow + 8) * PADH + k0], z2);
            __half2 v2 = __hmax2(*(const __half2*)&Xh[(arow)     * PADH + k0 + 8], z2);
            __half2 v3 = __hmax2(*(const __half2*)&Xh[(arow + 8) * PADH + k0 + 8], z2);
            a0 = *reinterpret_cast<uint32_t*>(&v0);
            a1 = *reinterpret_cast<uint32_t*>(&v1);
            a2 = *reinterpret_cast<uint32_t*>(&v2);
            a3 = *reinterpret_cast<uint32_t*>(&v3);
        } else {
            float2 f0 = *(const float2*)&Xf[(arow)     * PADF + k0];
            float2 f1 = *(const float2*)&Xf[(arow + 8) * PADF + k0];
            float2 f2 = *(const float2*)&Xf[(arow)     * PADF + k0 + 8];
            float2 f3 = *(const float2*)&Xf[(arow + 8) * PADF + k0 + 8];
            __half2 v0 = __floats2half2_rn(f0.x, f0.y);
            __half2 v1 = __floats2half2_rn(f1.x, f1.y);
            __half2 v2 = __floats2half2_rn(f2.x, f2.y);
            __half2 v3 = __floats2half2_rn(f3.x, f3.y);
            a0 = *reinterpret_cast<uint32_t*>(&v0);
            a1 = *reinterpret_cast<uint32_t*>(&v1);
            a2 = *reinterpret_cast<uint32_t*>(&v2);
            a3 = *reinterpret_cast<uint32_t*>(&v3);
        }
        #pragma unroll
        for (int n = 0; n < 8; n++) {
            int nc = n * 8 + grp;
            uint32_t b0 = *(const uint32_t*)&Wt[nc * 72 + k0];
            uint32_t b1 = *(const uint32_t*)&Wt[nc * 72 + k0 + 8];
            asm volatile(
                "mma.sync.aligned.m16n8k16.row.col.f32.f16.f16.f32 "
                "{%0,%1,%2,%3}, {%4,%5,%6,%7}, {%8,%9}, {%0,%1,%2,%3};"
                : "+f"(c[n][0]), "+f"(c[n][1]), "+f"(c[n][2]), "+f"(c[n][3])
                : "r"(a0), "r"(a1), "r"(a2), "r"(a3), "r"(b0), "r"(b1));
        }
    }

    // epilogue: scale by dinv[row], pack fp16, store
    int r0 = row0 + w * 16 + grp;
    int r1 = r0 + 8;
    float dv0 = (r0 < N_NODES) ? g_dinv[r0] : 0.f;
    float dv1 = (r1 < N_NODES) ? g_dinv[r1] : 0.f;
    #pragma unroll
    for (int n = 0; n < 8; n++) {
        int cw = n * 4 + qid;
        if (r0 < N_NODES)
            g_tmp_h[r0 * 32 + cw] = __floats2half2_rn(c[n][0] * dv0, c[n][1] * dv0);
        if (r1 < N_NODES)
            g_tmp_h[r1 * 32 + cw] = __floats2half2_rn(c[n][2] * dv1, c[n][3] * dv1);
    }
}

// -------- aggregation: warp per dst; gathers pre-scaled fp16 rows --------
template <bool TO_POOL>
__global__ void __launch_bounds__(256) k_agg(const float* __restrict__ bias,
                                             const int* __restrict__ batch) {
    int warp = (blockIdx.x * blockDim.x + threadIdx.x) >> 5;
    int lane = threadIdx.x & 31;
    if (warp >= N_NODES) return;
    int v = warp;
    float dv = g_dinv[v];

    float2 accn = __half22float2(g_tmp_h[v * 32 + lane]);  // self-loop (dv*h_v)
    int deg = g_cnt[v];
    if (deg > CAP) deg = CAP;
    const int* cols = &g_col[v * CAP];
    for (int base = 0; base < deg; base += 32) {
        int s = (base + lane < deg) ? cols[base + lane] : 0;
        int m = min(32, deg - base);
        int j = 0;
        for (; j + 4 <= m; j += 4) {
            int s0 = __shfl_sync(0xffffffffu, s, j);
            int s1 = __shfl_sync(0xffffffffu, s, j + 1);
            int s2 = __shfl_sync(0xffffffffu, s, j + 2);
            int s3 = __shfl_sync(0xffffffffu, s, j + 3);
            float2 f0 = __half22float2(g_tmp_h[s0 * 32 + lane]);
            float2 f1 = __half22float2(g_tmp_h[s1 * 32 + lane]);
            float2 f2 = __half22float2(g_tmp_h[s2 * 32 + lane]);
            float2 f3 = __half22float2(g_tmp_h[s3 * 32 + lane]);
            accn.x += (f0.x + f1.x) + (f2.x + f3.x);
            accn.y += (f0.y + f1.y) + (f2.y + f3.y);
        }
        for (; j < m; j++) {
            int sj = __shfl_sync(0xffffffffu, s, j);
            float2 f = __half22float2(g_tmp_h[sj * 32 + lane]);
            accn.x += f.x;
            accn.y += f.y;
        }
    }

    float2 acc;
    acc.x = dv * accn.x;
    acc.y = dv * accn.y;

    if (TO_POOL) {
        int g = batch[v];
        if ((unsigned)g < N_GRAPHS) {
            atomicAdd(&g_pool[g * 64 + lane * 2], acc.x);
            atomicAdd(&g_pool[g * 64 + lane * 2 + 1], acc.y);
        }
    } else {
        float2 b = *(const float2*)&bias[lane * 2];
        g_h_h[v * 32 + lane] = __floats2half2_rn(acc.x + b.x, acc.y + b.y);
    }
}

// -------- overflow edges (normally zero) --------
template <bool TO_POOL>
__global__ void k_ovf(const int* __restrict__ batch) {
    int n = g_novf;
    if (n > OVF_CAP) n = OVF_CAP;
    for (int idx = blockIdx.x * blockDim.x + threadIdx.x; idx < n * 32;
         idx += gridDim.x * blockDim.x) {
        int e = idx >> 5, lane = idx & 31;
        int2 ed = g_ovf[e];
        float w = g_dinv[ed.y];                                 // src dinv pre-baked
        float2 hs = __half22float2(g_tmp_h[ed.x * 32 + lane]);
        if (TO_POOL) {
            int g = batch[ed.y];
            if ((unsigned)g < N_GRAPHS) {
                atomicAdd(&g_pool[g * 64 + lane * 2], w * hs.x);
                atomicAdd(&g_pool[g * 64 + lane * 2 + 1], w * hs.y);
            }
        } else {
            atomicAdd(&g_h_h[ed.y * 32 + lane],
                      __floats2half2_rn(w * hs.x, w * hs.y));
        }
    }
}

// -------- head: mean = pool/cnt + b2; relu(mean@W3+b3) @ W4 + b4 --------
__global__ void k_head(const float* __restrict__ b2,
                       const float* __restrict__ W3, const float* __restrict__ b3,
                       const float* __restrict__ W4, const float* __restrict__ b4,
                       float* __restrict__ out) {
    int g = blockIdx.x;
    int j = threadIdx.x;
    __shared__ float mean[64];
    __shared__ float t[64];
    float c = (float)max(g_gcnt[g], 1);
    mean[j] = g_pool[g * 64 + j] / c + b2[j];
    __syncthreads();
    float acc = 0.f;
    #pragma unroll
    for (int k = 0; k < 64; k++) acc += mean[k] * W3[k * 64 + j];
    t[j] = fmaxf(acc + b3[j], 0.f) * W4[j];
    __syncthreads();
    if (j < 32) {
        float v = t[j] + t[j + 32];
        #pragma unroll
        for (int s = 16; s > 0; s >>= 1) v += __shfl_down_sync(0xffffffffu, v, s);
        if (j == 0) out[g] = v + b4[0];
    }
}

extern "C" void kernel_launch(void* const* d_in, const int* in_sizes, int n_in,
                              void* d_out, int out_size) {
    const float* x     = (const float*)d_in[0];
    const int*   ei    = (const int*)d_in[1];
    const int*   batch = (const int*)d_in[2];
    const float* W1    = (const float*)d_in[3];
    const float* b1    = (const float*)d_in[4];
    const float* W2    = (const float*)d_in[5];
    const float* b2    = (const float*)d_in[6];
    const float* W3    = (const float*)d_in[7];
    const float* b3    = (const float*)d_in[8];
    const float* W4    = (const float*)d_in[9];
    const float* b4    = (const float*)d_in[10];
    float* out = (float*)d_out;

    const int GEMM_BLOCKS = (N_NODES + 127) / 128;
    const int AGG_BLOCKS  = (N_NODES * 32 + 255) / 256;

    int init_blocks = (N_GRAPHS * DIM + 255) / 256 > (N_NODES + 255) / 256
                          ? (N_GRAPHS * DIM + 255) / 256
                          : (N_NODES + 255) / 256;
    k_init<<<init_blocks, 256>>>();
    k_build<<<(N_EDGES / 4 + 255) / 256, 256>>>(ei);
    k_dinv<<<(N_NODES + 255) / 256, 256>>>(batch);

    // layer 1
    k_gemm<false><<<GEMM_BLOCKS, 256>>>(x, W1);
    k_agg<false><<<AGG_BLOCKS, 256>>>(b1, batch);
    k_ovf<false><<<4, 256>>>(batch);

    // layer 2 (agg accumulates straight into g_pool)
    k_gemm<true><<<GEMM_BLOCKS, 256>>>(nullptr, W2);
    k_agg<true><<<AGG_BLOCKS, 256>>>(nullptr, batch);
    k_ovf<true><<<4, 256>>>(batch);

    k_head<<<N_GRAPHS, 64>>>(b2, W3, b3, W4, b4, out);
}